// round 3
// baseline (speedup 1.0000x reference)
#include <cuda_runtime.h>
#include <cstdint>
#include <cstddef>

#define TT 512
#define NBATCH 256
#define EE 256
#define HH 256
#define GG 1024
#define NBLK 128

// ---------------- device scratch (no allocations allowed) ----------------
__device__ __align__(16) float g_xg[(size_t)TT * NBATCH * GG];   // 512 MB: precomputed x@Wih^T + biases, layout [t][n][g]
__device__ __align__(16) float g_hbuf[2][NBATCH * HH];           // double-buffered h
__device__ unsigned int g_bar;                                   // monotonic ticket barrier

// ---------------- reset: graph-replay-safe state init ----------------
__global__ void __launch_bounds__(256) reset_kernel() {
    int idx = blockIdx.x * blockDim.x + threadIdx.x;
    if (idx < NBATCH * HH) g_hbuf[0][idx] = 0.0f;
    if (idx == 0) g_bar = 0u;
}

// ---------------- phase 1: xg = x @ Wih^T + b_ih + b_hh ----------------
// C[m][g], m = t*NBATCH + n.  Block tile 64(M) x 128(G), BK=32, 256 threads, 4x8 microtile.
__global__ void __launch_bounds__(256) xg_gemm_kernel(
    const float* __restrict__ attn,   // (N, T, E)
    const float* __restrict__ Wih,    // (4H, E)
    const float* __restrict__ bih,
    const float* __restrict__ bhh) {
    __shared__ float As[32][68];    // [k][m], padded
    __shared__ float Bs[32][132];   // [k][g], padded

    const int gt = blockIdx.x;          // gate tile 0..7
    const int mt = blockIdx.y;          // 0..2047
    const int t  = mt >> 2;
    const int n0 = (mt & 3) << 6;
    const int g0 = gt << 7;
    const int tid = threadIdx.x;
    const int ty = tid >> 4, tx = tid & 15;

    float acc[4][8];
#pragma unroll
    for (int i = 0; i < 4; i++)
#pragma unroll
        for (int j = 0; j < 8; j++) acc[i][j] = 0.0f;

    for (int k0 = 0; k0 < EE; k0 += 32) {
        {
            int row = tid >> 3, quad = tid & 7;
#pragma unroll
            for (int p = 0; p < 2; p++) {
                int r = row + (p << 5);
                float4 v = *(const float4*)&attn[((size_t)(n0 + r) * TT + t) * EE + k0 + (quad << 2)];
                int kk = quad << 2;
                As[kk + 0][r] = v.x; As[kk + 1][r] = v.y; As[kk + 2][r] = v.z; As[kk + 3][r] = v.w;
            }
        }
        {
            int gate = tid >> 1, kh = (tid & 1) << 4;
            const float* wp = &Wih[(size_t)(g0 + gate) * EE + k0 + kh];
#pragma unroll
            for (int j = 0; j < 4; j++) {
                float4 v = *(const float4*)&wp[j << 2];
                int kk = kh + (j << 2);
                Bs[kk + 0][gate] = v.x; Bs[kk + 1][gate] = v.y; Bs[kk + 2][gate] = v.z; Bs[kk + 3][gate] = v.w;
            }
        }
        __syncthreads();
#pragma unroll
        for (int k = 0; k < 32; k++) {
            float4 a4 = *(const float4*)&As[k][ty << 2];
            float4 b0 = *(const float4*)&Bs[k][tx << 3];
            float4 b1 = *(const float4*)&Bs[k][(tx << 3) + 4];
            float a[4] = {a4.x, a4.y, a4.z, a4.w};
            float b[8] = {b0.x, b0.y, b0.z, b0.w, b1.x, b1.y, b1.z, b1.w};
#pragma unroll
            for (int i = 0; i < 4; i++)
#pragma unroll
                for (int j = 0; j < 8; j++) acc[i][j] += a[i] * b[j];
        }
        __syncthreads();
    }

    float bias[8];
#pragma unroll
    for (int j = 0; j < 8; j++) {
        int g = g0 + (tx << 3) + j;
        bias[j] = bih[g] + bhh[g];
    }
#pragma unroll
    for (int i = 0; i < 4; i++) {
        int n = n0 + (ty << 2) + i;
        size_t base = ((size_t)t * NBATCH + n) * GG + g0 + (tx << 3);
        float4 o0 = make_float4(acc[i][0] + bias[0], acc[i][1] + bias[1],
                                acc[i][2] + bias[2], acc[i][3] + bias[3]);
        float4 o1 = make_float4(acc[i][4] + bias[4], acc[i][5] + bias[5],
                                acc[i][6] + bias[6], acc[i][7] + bias[7]);
        *(float4*)&g_xg[base]     = o0;
        *(float4*)&g_xg[base + 4] = o1;
    }
}

// ---------------- phase 2: persistent recurrent kernel ----------------
__device__ __forceinline__ float sigf(float x) { return 1.0f / (1.0f + __expf(-x)); }
__device__ __forceinline__ float tanh_fast(float x) { return 1.0f - 2.0f / (__expf(2.0f * x) + 1.0f); }

// 128 blocks: bn = bid & 15 (16 batch rows each), bj = bid >> 4 (32 h-cols x 4 gate types each)
// 256 threads: warp ks = tid>>5 owns K-slice [ks*32, ks*32+32); lane gcg = tid&31 owns 4 local gates.
// W_hh slice lives entirely in registers (128 regs/thread).
__global__ void __launch_bounds__(256, 1) lstm_rec_kernel(
    const float* __restrict__ Whh,       // (4H, H)
    const int*   __restrict__ traj_len,  // (N,)
    float*       __restrict__ out) {     // (N, 1, H)
    extern __shared__ float red[];       // [8][16][128] = 64 KB

    const int tid = threadIdx.x;
    const int bid = blockIdx.x;
    const int bn = bid & 15, bj = bid >> 4;
    const int r0 = bn << 4;        // batch row base
    const int c0 = bj << 5;        // h-col base
    const int ks = tid >> 5, gcg = tid & 31;

    // load private W_hh slice into registers
    float4 w[32];
#pragma unroll
    for (int q = 0; q < 4; q++) {
        int l = (gcg << 2) + q;                      // local gate index 0..127
        int gr = ((l >> 5) << 8) + c0 + (l & 31);    // global gate row
        const float4* wp = (const float4*)&Whh[(size_t)gr * HH + (ks << 5)];
#pragma unroll
        for (int kc = 0; kc < 8; kc++) w[(q << 3) + kc] = wp[kc];
    }

    // elementwise ownership: thread owns 2 cells (row er, cols ep*2, ep*2+1)
    const int er = tid >> 4, ep = tid & 15;
    const int n_e = r0 + er;
    const int len_e = traj_len[n_e];
    const int col_e = c0 + (ep << 1);
    float cc0 = 0.f, cc1 = 0.f, hk0 = 0.f, hk1 = 0.f;

    for (int t = 0; t < TT; t++) {
        // Prefetch this step's xg BEFORE the barrier: recurrence-independent,
        // overlaps the spin-wait latency.
        const float* xgp = &g_xg[((size_t)t * NBATCH + n_e) * GG + col_e];
        float2 xi  = __ldcs((const float2*)&xgp[0]);
        float2 xf  = __ldcs((const float2*)&xgp[256]);
        float2 xg2 = __ldcs((const float2*)&xgp[512]);
        float2 xo  = __ldcs((const float2*)&xgp[768]);

        if (t > 0) {
            if (tid == 0) {
                unsigned target = (unsigned)t * NBLK;
                while (*((volatile unsigned int*)&g_bar) < target) { __nanosleep(64); }
            }
            __syncthreads();
        }
        const float* hb = g_hbuf[t & 1];

        // GEMM partials: gates_partial[r][l] over this warp's K-slice
#pragma unroll 2
        for (int r = 0; r < 16; r++) {
            const float4* hp = (const float4*)&hb[((r0 + r) << 8) + (ks << 5)];
            float ax = 0.f, ay = 0.f, az = 0.f, aw = 0.f;
#pragma unroll
            for (int kc = 0; kc < 8; kc++) {
                float4 hv = __ldcg(hp + kc);
                ax += hv.x * w[kc].x      + hv.y * w[kc].y      + hv.z * w[kc].z      + hv.w * w[kc].w;
                ay += hv.x * w[8 + kc].x  + hv.y * w[8 + kc].y  + hv.z * w[8 + kc].z  + hv.w * w[8 + kc].w;
                az += hv.x * w[16 + kc].x + hv.y * w[16 + kc].y + hv.z * w[16 + kc].z + hv.w * w[16 + kc].w;
                aw += hv.x * w[24 + kc].x + hv.y * w[24 + kc].y + hv.z * w[24 + kc].z + hv.w * w[24 + kc].w;
            }
            *(float4*)&red[(((ks << 4) + r) << 7) + (gcg << 2)] = make_float4(ax, ay, az, aw);
        }
        __syncthreads();

        // reduce over 8 K-slices for this thread's 2 cells, all 4 gate types
        float2 s[4];
#pragma unroll
        for (int typ = 0; typ < 4; typ++) {
            float sx = 0.f, sy = 0.f;
#pragma unroll
            for (int k2 = 0; k2 < 8; k2++) {
                float2 v = *(const float2*)&red[(k2 << 11) + (er << 7) + (typ << 5) + (ep << 1)];
                sx += v.x; sy += v.y;
            }
            s[typ] = make_float2(sx, sy);
        }

        const bool valid = (t < len_e);
        {
            float gi = s[0].x + xi.x, gf = s[1].x + xf.x, gg = s[2].x + xg2.x, go = s[3].x + xo.x;
            float cn = sigf(gf) * cc0 + sigf(gi) * tanh_fast(gg);
            float hn = sigf(go) * tanh_fast(cn);
            if (valid) { cc0 = cn; hk0 = hn; }
        }
        {
            float gi = s[0].y + xi.y, gf = s[1].y + xf.y, gg = s[2].y + xg2.y, go = s[3].y + xo.y;
            float cn = sigf(gf) * cc1 + sigf(gi) * tanh_fast(gg);
            float hn = sigf(go) * tanh_fast(cn);
            if (valid) { cc1 = cn; hk1 = hn; }
        }

        // publish h for next step (frozen rows republished, keeps both buffers valid)
        *(float2*)&g_hbuf[(t + 1) & 1][(n_e << 8) + col_e] = make_float2(hk0, hk1);

        __threadfence();
        __syncthreads();
        if (tid == 0) atomicAdd(&g_bar, 1u);
    }

    *(float2*)&out[(n_e << 8) + col_e] = make_float2(hk0, hk1);
}

// ---------------- launch ----------------
extern "C" void kernel_launch(void* const* d_in, const int* in_sizes, int n_in,
                              void* d_out, int out_size) {
    const float* attn     = (const float*)d_in[0];   // (N, T, E)
    const int*   traj_len = (const int*)d_in[1];     // (N,)
    const float* Wih      = (const float*)d_in[2];   // (4H, E)
    const float* Whh      = (const float*)d_in[3];   // (4H, H)
    const float* bih      = (const float*)d_in[4];   // (4H,)
    const float* bhh      = (const float*)d_in[5];   // (4H,)
    float* out = (float*)d_out;

    cudaFuncSetAttribute(lstm_rec_kernel, cudaFuncAttributeMaxDynamicSharedMemorySize, 65536);

    reset_kernel<<<256, 256>>>();

    dim3 g1(8, 2048);
    xg_gemm_kernel<<<g1, 256>>>(attn, Wih, bih, bhh);

    lstm_rec_kernel<<<NBLK, 256, 65536>>>(Whh, traj_len, out);

    (void)in_sizes; (void)n_in; (void)out_size;
}

// round 5
// speedup vs baseline: 1.2517x; 1.2517x over previous
#include <cuda_runtime.h>
#include <cstdint>
#include <cstddef>

#define TT 512
#define NBATCH 256
#define EE 256
#define HH 256
#define GG 1024
#define NBLK 128

// ---------------- device scratch (no allocations allowed) ----------------
__device__ __align__(16) float g_xg[(size_t)TT * NBATCH * GG];   // 512 MB: xg[t][n][g] = x@Wih^T + b_ih + b_hh
__device__ __align__(16) float g_hbuf[2][NBATCH * HH];           // double-buffered h
__device__ unsigned int g_bar;                                   // monotonic ticket barrier

// ---------------- reset: graph-replay-safe state init ----------------
__global__ void __launch_bounds__(256) reset_kernel() {
    int idx = blockIdx.x * blockDim.x + threadIdx.x;
    if (idx < NBATCH * HH) g_hbuf[0][idx] = 0.0f;
    if (idx == 0) g_bar = 0u;
}

// ---------------- phase 1: xg = x @ Wih^T + b_ih + b_hh ----------------
// 128(M) x 128(G) block tile, BK=16, 256 threads, 8x8 microtile in 2x2 split
// fragments, double-buffered smem, 1 syncthreads per k-tile.
// M-row m = t*NBATCH + n;  a block covers one t and 128 consecutive n.
__global__ void __launch_bounds__(256, 2) xg_gemm_kernel(
    const float* __restrict__ attn,   // (N, T, E)
    const float* __restrict__ Wih,    // (4H, E)
    const float* __restrict__ bih,
    const float* __restrict__ bhh) {
    __shared__ float As[2][16][132];   // [buf][k][m]
    __shared__ float Bs[2][16][132];   // [buf][k][g]

    const int gt = blockIdx.x;                 // 0..7
    const int mt = blockIdx.y;                 // 0..1023
    const int t  = mt >> 1;
    const int n0 = (mt & 1) << 7;
    const int g0 = gt << 7;
    const int tid = threadIdx.x;
    const int tx = tid & 15;
    const int tyy = tid >> 4;                  // 0..15

    // loader assignment: 2 threads per row, 8 k each (2 float4)
    const int lr = tid >> 1;                   // row 0..127
    const int lk = (tid & 1) << 3;             // k offset 0 or 8

    const float* Arow = &attn[((size_t)(n0 + lr) * TT + t) * EE];
    const float* Brow = &Wih[(size_t)(g0 + lr) * EE];

    float acc[8][8];
#pragma unroll
    for (int i = 0; i < 8; i++)
#pragma unroll
        for (int j = 0; j < 8; j++) acc[i][j] = 0.0f;

    float4 a0, a1, b0, b1;

    // prologue: tile 0
    a0 = *(const float4*)&Arow[lk];
    a1 = *(const float4*)&Arow[lk + 4];
    b0 = *(const float4*)&Brow[lk];
    b1 = *(const float4*)&Brow[lk + 4];
    {
        float av[8] = {a0.x, a0.y, a0.z, a0.w, a1.x, a1.y, a1.z, a1.w};
        float bv[8] = {b0.x, b0.y, b0.z, b0.w, b1.x, b1.y, b1.z, b1.w};
#pragma unroll
        for (int q = 0; q < 8; q++) { As[0][lk + q][lr] = av[q]; Bs[0][lk + q][lr] = bv[q]; }
    }
    __syncthreads();

    const int NKT = EE / 16;   // 16 tiles
#pragma unroll 1
    for (int kt = 0; kt < NKT; kt++) {
        const int cur = kt & 1, nxt = cur ^ 1;
        if (kt + 1 < NKT) {
            const int k0 = (kt + 1) << 4;
            a0 = *(const float4*)&Arow[k0 + lk];
            a1 = *(const float4*)&Arow[k0 + lk + 4];
            b0 = *(const float4*)&Brow[k0 + lk];
            b1 = *(const float4*)&Brow[k0 + lk + 4];
        }
#pragma unroll
        for (int k = 0; k < 16; k++) {
            float4 aA = *(const float4*)&As[cur][k][tyy << 2];
            float4 aB = *(const float4*)&As[cur][k][64 + (tyy << 2)];
            float4 bA = *(const float4*)&Bs[cur][k][tx << 2];
            float4 bB = *(const float4*)&Bs[cur][k][64 + (tx << 2)];
            float a[8] = {aA.x, aA.y, aA.z, aA.w, aB.x, aB.y, aB.z, aB.w};
            float b[8] = {bA.x, bA.y, bA.z, bA.w, bB.x, bB.y, bB.z, bB.w};
#pragma unroll
            for (int i = 0; i < 8; i++)
#pragma unroll
                for (int j = 0; j < 8; j++) acc[i][j] += a[i] * b[j];
        }
        if (kt + 1 < NKT) {
            float av[8] = {a0.x, a0.y, a0.z, a0.w, a1.x, a1.y, a1.z, a1.w};
            float bv[8] = {b0.x, b0.y, b0.z, b0.w, b1.x, b1.y, b1.z, b1.w};
#pragma unroll
            for (int q = 0; q < 8; q++) { As[nxt][lk + q][lr] = av[q]; Bs[nxt][lk + q][lr] = bv[q]; }
        }
        __syncthreads();
    }

    // epilogue: bias + store
    float bias[2][4];
#pragma unroll
    for (int jh = 0; jh < 2; jh++)
#pragma unroll
        for (int j = 0; j < 4; j++) {
            int g = g0 + (jh << 6) + (tx << 2) + j;
            bias[jh][j] = bih[g] + bhh[g];
        }
#pragma unroll
    for (int ih = 0; ih < 2; ih++)
#pragma unroll
        for (int i = 0; i < 4; i++) {
            int n = n0 + (ih << 6) + (tyy << 2) + i;
            size_t base = ((size_t)t * NBATCH + n) * GG + g0;
            int r = (ih << 2) + i;
            float4 v0 = make_float4(acc[r][0] + bias[0][0], acc[r][1] + bias[0][1],
                                    acc[r][2] + bias[0][2], acc[r][3] + bias[0][3]);
            float4 v1 = make_float4(acc[r][4] + bias[1][0], acc[r][5] + bias[1][1],
                                    acc[r][6] + bias[1][2], acc[r][7] + bias[1][3]);
            *(float4*)&g_xg[base + (tx << 2)]      = v0;
            *(float4*)&g_xg[base + 64 + (tx << 2)] = v1;
        }
}

// ---------------- phase 2: persistent recurrent kernel ----------------
__device__ __forceinline__ float sigf(float x) { return 1.0f / (1.0f + __expf(-x)); }
__device__ __forceinline__ float tanh_fast(float x) { return 1.0f - 2.0f / (__expf(2.0f * x) + 1.0f); }

// 128 blocks: bn = bid & 15 (16 batch rows), bj = bid >> 4 (32 h-cols x 4 gate types)
// 256 threads: warp ks owns K-slice; lane owns 4 local gates. Whh slice in registers.
__global__ void __launch_bounds__(256, 1) lstm_rec_kernel(
    const float* __restrict__ Whh,       // (4H, H)
    const int*   __restrict__ traj_len,  // (N,)
    float*       __restrict__ out) {     // (N, 1, H)
    extern __shared__ float red[];       // [8][16][128] = 64 KB

    const int tid = threadIdx.x;
    const int bid = blockIdx.x;
    const int bn = bid & 15, bj = bid >> 4;
    const int r0 = bn << 4;
    const int c0 = bj << 5;
    const int ks = tid >> 5, gcg = tid & 31;

    float4 w[32];
#pragma unroll
    for (int q = 0; q < 4; q++) {
        int l = (gcg << 2) + q;
        int gr = ((l >> 5) << 8) + c0 + (l & 31);
        const float4* wp = (const float4*)&Whh[(size_t)gr * HH + (ks << 5)];
#pragma unroll
        for (int kc = 0; kc < 8; kc++) w[(q << 3) + kc] = wp[kc];
    }

    const int er = tid >> 4, ep = tid & 15;
    const int n_e = r0 + er;
    const int len_e = traj_len[n_e];
    const int col_e = c0 + (ep << 1);
    float cc0 = 0.f, cc1 = 0.f, hk0 = 0.f, hk1 = 0.f;

    unsigned int* barp = &g_bar;

    for (int t = 0; t < TT; t++) {
        // prefetch xg(t) before the spin: recurrence-independent
        const float* xgp = &g_xg[((size_t)t * NBATCH + n_e) * GG + col_e];
        float2 xi  = __ldcs((const float2*)&xgp[0]);
        float2 xf  = __ldcs((const float2*)&xgp[256]);
        float2 xg2 = __ldcs((const float2*)&xgp[512]);
        float2 xo  = __ldcs((const float2*)&xgp[768]);

        if (t > 0) {
            if (tid == 0) {
                const unsigned target = (unsigned)t * NBLK;
                unsigned v;
                do {
                    asm volatile("ld.acquire.gpu.global.u32 %0, [%1];"
                                 : "=r"(v) : "l"(barp) : "memory");
                    if (v < target) __nanosleep(32);
                } while (v < target);
            }
            __syncthreads();
        }
        const float* hb = g_hbuf[t & 1];

#pragma unroll 2
        for (int r = 0; r < 16; r++) {
            const float4* hp = (const float4*)&hb[((r0 + r) << 8) + (ks << 5)];
            float ax = 0.f, ay = 0.f, az = 0.f, aw = 0.f;
#pragma unroll
            for (int kc = 0; kc < 8; kc++) {
                float4 hv = __ldcg(hp + kc);
                ax += hv.x * w[kc].x      + hv.y * w[kc].y      + hv.z * w[kc].z      + hv.w * w[kc].w;
                ay += hv.x * w[8 + kc].x  + hv.y * w[8 + kc].y  + hv.z * w[8 + kc].z  + hv.w * w[8 + kc].w;
                az += hv.x * w[16 + kc].x + hv.y * w[16 + kc].y + hv.z * w[16 + kc].z + hv.w * w[16 + kc].w;
                aw += hv.x * w[24 + kc].x + hv.y * w[24 + kc].y + hv.z * w[24 + kc].z + hv.w * w[24 + kc].w;
            }
            *(float4*)&red[(((ks << 4) + r) << 7) + (gcg << 2)] = make_float4(ax, ay, az, aw);
        }
        __syncthreads();

        float2 s[4];
#pragma unroll
        for (int typ = 0; typ < 4; typ++) {
            float sx = 0.f, sy = 0.f;
#pragma unroll
            for (int k2 = 0; k2 < 8; k2++) {
                float2 v = *(const float2*)&red[(k2 << 11) + (er << 7) + (typ << 5) + (ep << 1)];
                sx += v.x; sy += v.y;
            }
            s[typ] = make_float2(sx, sy);
        }

        const bool valid = (t < len_e);
        {
            float gi = s[0].x + xi.x, gf = s[1].x + xf.x, gg = s[2].x + xg2.x, go = s[3].x + xo.x;
            float cn = sigf(gf) * cc0 + sigf(gi) * tanh_fast(gg);
            float hn = sigf(go) * tanh_fast(cn);
            if (valid) { cc0 = cn; hk0 = hn; }
        }
        {
            float gi = s[0].y + xi.y, gf = s[1].y + xf.y, gg = s[2].y + xg2.y, go = s[3].y + xo.y;
            float cn = sigf(gf) * cc1 + sigf(gi) * tanh_fast(gg);
            float hn = sigf(go) * tanh_fast(cn);
            if (valid) { cc1 = cn; hk1 = hn; }
        }

        *(float2*)&g_hbuf[(t + 1) & 1][(n_e << 8) + col_e] = make_float2(hk0, hk1);

        __syncthreads();
        if (tid == 0) {
            // release-arrive: syncthreads above makes all CTA stores visible to
            // thread 0; the release-reduction publishes them at gpu scope.
            asm volatile("red.release.gpu.global.add.u32 [%0], %1;"
                         :: "l"(barp), "r"(1u) : "memory");
        }
    }

    *(float2*)&out[(n_e << 8) + col_e] = make_float2(hk0, hk1);
}

// ---------------- launch ----------------
extern "C" void kernel_launch(void* const* d_in, const int* in_sizes, int n_in,
                              void* d_out, int out_size) {
    const float* attn     = (const float*)d_in[0];   // (N, T, E)
    const int*   traj_len = (const int*)d_in[1];     // (N,)
    const float* Wih      = (const float*)d_in[2];   // (4H, E)
    const float* Whh      = (const float*)d_in[3];   // (4H, H)
    const float* bih      = (const float*)d_in[4];   // (4H,)
    const float* bhh      = (const float*)d_in[5];   // (4H,)
    float* out = (float*)d_out;

    cudaFuncSetAttribute(lstm_rec_kernel, cudaFuncAttributeMaxDynamicSharedMemorySize, 65536);

    reset_kernel<<<256, 256>>>();

    dim3 g1(8, 1024);
    xg_gemm_kernel<<<g1, 256>>>(attn, Wih, bih, bhh);

    lstm_rec_kernel<<<NBLK, 256, 65536>>>(Whh, traj_len, out);

    (void)in_sizes; (void)n_in; (void)out_size;
}

// round 6
// speedup vs baseline: 1.4817x; 1.1838x over previous
#include <cuda_runtime.h>
#include <cstdint>
#include <cstddef>

#define TT 512
#define NBATCH 256
#define EE 256
#define HH 256
#define GG 1024
#define NBLK 128

typedef unsigned long long ull;
union F2U { ull u; float2 f; };

// ---- packed f32x2 helpers (Blackwell FFMA2 — PTX-only, ptxas never fuses) ----
__device__ __forceinline__ ull bcast2(float x) {
    ull r; asm("mov.b64 %0, {%1, %1};" : "=l"(r) : "f"(x)); return r;
}
__device__ __forceinline__ ull pack2(float lo, float hi) {
    ull r; asm("mov.b64 %0, {%1, %2};" : "=l"(r) : "f"(lo), "f"(hi)); return r;
}
__device__ __forceinline__ void ffma2(ull& d, ull a, ull b) {
    asm("fma.rn.f32x2 %0, %1, %2, %0;" : "+l"(d) : "l"(a), "l"(b));
}

// ---------------- device scratch (no allocations allowed) ----------------
__device__ __align__(16) float g_xg[(size_t)TT * NBATCH * GG];   // xg[t][n][g] = x@Wih^T + b_ih + b_hh
__device__ __align__(16) float g_hbuf[2][NBATCH * HH];           // double-buffered h
__device__ unsigned int g_bar;                                   // monotonic ticket barrier

// ---------------- reset: graph-replay-safe state init ----------------
__global__ void __launch_bounds__(256) reset_kernel() {
    int idx = blockIdx.x * blockDim.x + threadIdx.x;
    if (idx < NBATCH * HH) g_hbuf[0][idx] = 0.0f;
    if (idx == 0) g_bar = 0u;
}

// ---------------- phase 1: xg = x @ Wih^T + b_ih + b_hh ----------------
// 128x128 block tile, BK=16, 256 threads, 8x8 microtile held as 4 row-pairs x 8
// cols of f32x2 accumulators (FFMA2). Row-pairs reinterpret adjacent smem floats;
// B-side broadcast-packed per k. Double-buffered smem, 1 sync per k-tile.
__global__ void __launch_bounds__(256, 2) xg_gemm_kernel(
    const float* __restrict__ attn,   // (N, T, E)
    const float* __restrict__ Wih,    // (4H, E)
    const float* __restrict__ bih,
    const float* __restrict__ bhh) {
    __shared__ float As[2][16][132];   // [buf][k][m]
    __shared__ float Bs[2][16][132];   // [buf][k][g]

    const int gt = blockIdx.x;                 // 0..7
    const int mt = blockIdx.y;                 // 0..1023
    const int t  = mt >> 1;
    const int n0 = (mt & 1) << 7;
    const int g0 = gt << 7;
    const int tid = threadIdx.x;
    const int tx = tid & 15;
    const int tyy = tid >> 4;                  // 0..15

    const int lr = tid >> 1;                   // loader row 0..127
    const int lk = (tid & 1) << 3;             // k offset 0 or 8

    const float* Arow = &attn[((size_t)(n0 + lr) * TT + t) * EE];
    const float* Brow = &Wih[(size_t)(g0 + lr) * EE];

    ull acc2[4][8];                            // [row-pair][gate col], f32x2
#pragma unroll
    for (int i = 0; i < 4; i++)
#pragma unroll
        for (int j = 0; j < 8; j++) acc2[i][j] = 0ull;

    float4 a0, a1, b0, b1;

    // prologue: tile 0
    a0 = *(const float4*)&Arow[lk];
    a1 = *(const float4*)&Arow[lk + 4];
    b0 = *(const float4*)&Brow[lk];
    b1 = *(const float4*)&Brow[lk + 4];
    {
        float av[8] = {a0.x, a0.y, a0.z, a0.w, a1.x, a1.y, a1.z, a1.w};
        float bv[8] = {b0.x, b0.y, b0.z, b0.w, b1.x, b1.y, b1.z, b1.w};
#pragma unroll
        for (int q = 0; q < 8; q++) { As[0][lk + q][lr] = av[q]; Bs[0][lk + q][lr] = bv[q]; }
    }
    __syncthreads();

    const int NKT = EE / 16;   // 16 tiles
#pragma unroll 1
    for (int kt = 0; kt < NKT; kt++) {
        const int cur = kt & 1, nxt = cur ^ 1;
        if (kt + 1 < NKT) {
            const int k0 = (kt + 1) << 4;
            a0 = *(const float4*)&Arow[k0 + lk];
            a1 = *(const float4*)&Arow[k0 + lk + 4];
            b0 = *(const float4*)&Brow[k0 + lk];
            b1 = *(const float4*)&Brow[k0 + lk + 4];
        }
#pragma unroll
        for (int k = 0; k < 16; k++) {
            ulonglong2 aP0 = *(const ulonglong2*)&As[cur][k][tyy << 2];         // rows +0,+1 | +2,+3
            ulonglong2 aP1 = *(const ulonglong2*)&As[cur][k][64 + (tyy << 2)];  // rows 64+...
            ull ap[4] = {aP0.x, aP0.y, aP1.x, aP1.y};
            float4 bA = *(const float4*)&Bs[cur][k][tx << 2];
            float4 bB = *(const float4*)&Bs[cur][k][64 + (tx << 2)];
            ull bb[8] = {bcast2(bA.x), bcast2(bA.y), bcast2(bA.z), bcast2(bA.w),
                         bcast2(bB.x), bcast2(bB.y), bcast2(bB.z), bcast2(bB.w)};
#pragma unroll
            for (int ip = 0; ip < 4; ip++)
#pragma unroll
                for (int j = 0; j < 8; j++) ffma2(acc2[ip][j], ap[ip], bb[j]);
        }
        if (kt + 1 < NKT) {
            float av[8] = {a0.x, a0.y, a0.z, a0.w, a1.x, a1.y, a1.z, a1.w};
            float bv[8] = {b0.x, b0.y, b0.z, b0.w, b1.x, b1.y, b1.z, b1.w};
#pragma unroll
            for (int q = 0; q < 8; q++) { As[nxt][lk + q][lr] = av[q]; Bs[nxt][lk + q][lr] = bv[q]; }
        }
        __syncthreads();
    }

    // epilogue: bias + store
    float bias[2][4];
#pragma unroll
    for (int jh = 0; jh < 2; jh++)
#pragma unroll
        for (int j = 0; j < 4; j++) {
            int g = g0 + (jh << 6) + (tx << 2) + j;
            bias[jh][j] = bih[g] + bhh[g];
        }
#pragma unroll
    for (int rr = 0; rr < 8; rr++) {
        const int ih = rr >> 2, i = rr & 3;
        const int ip = (ih << 1) | (i >> 1);
        const int hi = i & 1;
        int n = n0 + (ih << 6) + (tyy << 2) + i;
        size_t base = ((size_t)t * NBATCH + n) * GG + g0;
        float c[8];
#pragma unroll
        for (int j = 0; j < 8; j++) {
            F2U u; u.u = acc2[ip][j];
            c[j] = hi ? u.f.y : u.f.x;
        }
        float4 v0 = make_float4(c[0] + bias[0][0], c[1] + bias[0][1],
                                c[2] + bias[0][2], c[3] + bias[0][3]);
        float4 v1 = make_float4(c[4] + bias[1][0], c[5] + bias[1][1],
                                c[6] + bias[1][2], c[7] + bias[1][3]);
        *(float4*)&g_xg[base + (tx << 2)]      = v0;
        *(float4*)&g_xg[base + 64 + (tx << 2)] = v1;
    }
}

// ---------------- phase 2: persistent recurrent kernel ----------------
__device__ __forceinline__ float sigf(float x) { return 1.0f / (1.0f + __expf(-x)); }
__device__ __forceinline__ float tanh_fast(float x) { return 1.0f - 2.0f / (__expf(2.0f * x) + 1.0f); }

// 128 blocks: bn = bid & 15 (16 batch rows), bj = bid >> 4 (32 h-cols x 4 gate types)
// 256 threads: warp ks owns K-slice; lane owns 4 consecutive same-type gate cols,
// weights pre-packed into f32x2 gate-pairs in registers. Frozen rows (t >= len)
// are skipped entirely (warp-uniform branch) — their outputs are final.
__global__ void __launch_bounds__(256, 1) lstm_rec_kernel(
    const float* __restrict__ Whh,       // (4H, H)
    const int*   __restrict__ traj_len,  // (N,)
    float*       __restrict__ out) {     // (N, 1, H)
    extern __shared__ float red[];       // [8][16][128] = 64 KB
    __shared__ int slen[16];

    const int tid = threadIdx.x;
    const int bid = blockIdx.x;
    const int bn = bid & 15, bj = bid >> 4;
    const int r0 = bn << 4;
    const int c0 = bj << 5;
    const int ks = tid >> 5, gcg = tid & 31;

    // pack W_hh slice into f32x2 gate-pair registers:
    // pwA[kc*4+c] = {W[q0][k], W[q1][k]},  pwB = {W[q2][k], W[q3][k]},  k = ks*32+kc*4+c
    ull pwA[32], pwB[32];
    {
        const float* wr[4];
#pragma unroll
        for (int q = 0; q < 4; q++) {
            int l = (gcg << 2) + q;
            int gr = ((l >> 5) << 8) + c0 + (l & 31);
            wr[q] = &Whh[(size_t)gr * HH + (ks << 5)];
        }
#pragma unroll
        for (int kc = 0; kc < 8; kc++) {
            float4 w0 = *(const float4*)(wr[0] + (kc << 2));
            float4 w1 = *(const float4*)(wr[1] + (kc << 2));
            float4 w2 = *(const float4*)(wr[2] + (kc << 2));
            float4 w3 = *(const float4*)(wr[3] + (kc << 2));
            pwA[(kc << 2) + 0] = pack2(w0.x, w1.x);
            pwA[(kc << 2) + 1] = pack2(w0.y, w1.y);
            pwA[(kc << 2) + 2] = pack2(w0.z, w1.z);
            pwA[(kc << 2) + 3] = pack2(w0.w, w1.w);
            pwB[(kc << 2) + 0] = pack2(w2.x, w3.x);
            pwB[(kc << 2) + 1] = pack2(w2.y, w3.y);
            pwB[(kc << 2) + 2] = pack2(w2.z, w3.z);
            pwB[(kc << 2) + 3] = pack2(w2.w, w3.w);
        }
    }

    if (tid < 16) slen[tid] = traj_len[r0 + tid];

    const int er = tid >> 4, ep = tid & 15;
    const int n_e = r0 + er;
    const int len_e = traj_len[n_e];
    const int col_e = c0 + (ep << 1);
    float cc0 = 0.f, cc1 = 0.f, hk0 = 0.f, hk1 = 0.f;

    unsigned int* barp = &g_bar;
    __syncthreads();   // slen visible before first partial loop

    for (int t = 0; t < TT; t++) {
        const bool valid = (t < len_e);

        // prefetch xg(t) before the spin (recurrence-independent, active rows only)
        float2 xi, xf, xg2, xo;
        if (valid) {
            const float* xgp = &g_xg[((size_t)t * NBATCH + n_e) * GG + col_e];
            xi  = __ldcs((const float2*)&xgp[0]);
            xf  = __ldcs((const float2*)&xgp[256]);
            xg2 = __ldcs((const float2*)&xgp[512]);
            xo  = __ldcs((const float2*)&xgp[768]);
        }

        if (t > 0) {
            if (tid == 0) {
                const unsigned target = (unsigned)t * NBLK;
                unsigned v;
                do {
                    asm volatile("ld.acquire.gpu.global.u32 %0, [%1];"
                                 : "=r"(v) : "l"(barp) : "memory");
                    if (v < target) __nanosleep(32);
                } while (v < target);
            }
            __syncthreads();
        }
        const float* hb = g_hbuf[t & 1];

        // GEMM partials over this warp's K-slice — skip frozen rows (uniform branch)
#pragma unroll 2
        for (int r = 0; r < 16; r++) {
            if (t < slen[r]) {
                const float4* hp = (const float4*)&hb[((r0 + r) << 8) + (ks << 5)];
                ull accA = 0ull, accB = 0ull;
#pragma unroll
                for (int kc = 0; kc < 8; kc++) {
                    float4 hv = __ldcg(hp + kc);
                    ull h0 = bcast2(hv.x), h1 = bcast2(hv.y), h2 = bcast2(hv.z), h3 = bcast2(hv.w);
                    ffma2(accA, h0, pwA[(kc << 2) + 0]); ffma2(accB, h0, pwB[(kc << 2) + 0]);
                    ffma2(accA, h1, pwA[(kc << 2) + 1]); ffma2(accB, h1, pwB[(kc << 2) + 1]);
                    ffma2(accA, h2, pwA[(kc << 2) + 2]); ffma2(accB, h2, pwB[(kc << 2) + 2]);
                    ffma2(accA, h3, pwA[(kc << 2) + 3]); ffma2(accB, h3, pwB[(kc << 2) + 3]);
                }
                ulonglong2 st; st.x = accA; st.y = accB;
                *(ulonglong2*)&red[(((ks << 4) + r) << 7) + (gcg << 2)] = st;
            }
        }
        __syncthreads();

        if (valid) {
            float2 s[4];
#pragma unroll
            for (int typ = 0; typ < 4; typ++) {
                float sx = 0.f, sy = 0.f;
#pragma unroll
                for (int k2 = 0; k2 < 8; k2++) {
                    float2 v = *(const float2*)&red[(k2 << 11) + (er << 7) + (typ << 5) + (ep << 1)];
                    sx += v.x; sy += v.y;
                }
                s[typ] = make_float2(sx, sy);
            }
            {
                float gi = s[0].x + xi.x, gf = s[1].x + xf.x, gg = s[2].x + xg2.x, go = s[3].x + xo.x;
                float cn = sigf(gf) * cc0 + sigf(gi) * tanh_fast(gg);
                cc0 = cn; hk0 = sigf(go) * tanh_fast(cn);
            }
            {
                float gi = s[0].y + xi.y, gf = s[1].y + xf.y, gg = s[2].y + xg2.y, go = s[3].y + xo.y;
                float cn = sigf(gf) * cc1 + sigf(gi) * tanh_fast(gg);
                cc1 = cn; hk1 = sigf(go) * tanh_fast(cn);
            }
        }

        // publish h for next step (frozen rows republish last value)
        *(float2*)&g_hbuf[(t + 1) & 1][(n_e << 8) + col_e] = make_float2(hk0, hk1);

        __syncthreads();
        if (tid == 0) {
            asm volatile("red.release.gpu.global.add.u32 [%0], %1;"
                         :: "l"(barp), "r"(1u) : "memory");
        }
    }

    *(float2*)&out[(n_e << 8) + col_e] = make_float2(hk0, hk1);
}

// ---------------- launch ----------------
extern "C" void kernel_launch(void* const* d_in, const int* in_sizes, int n_in,
                              void* d_out, int out_size) {
    const float* attn     = (const float*)d_in[0];   // (N, T, E)
    const int*   traj_len = (const int*)d_in[1];     // (N,)
    const float* Wih      = (const float*)d_in[2];   // (4H, E)
    const float* Whh      = (const float*)d_in[3];   // (4H, H)
    const float* bih      = (const float*)d_in[4];   // (4H,)
    const float* bhh      = (const float*)d_in[5];   // (4H,)
    float* out = (float*)d_out;

    cudaFuncSetAttribute(lstm_rec_kernel, cudaFuncAttributeMaxDynamicSharedMemorySize, 65536);

    reset_kernel<<<256, 256>>>();

    dim3 g1(8, 1024);
    xg_gemm_kernel<<<g1, 256>>>(attn, Wih, bih, bhh);

    lstm_rec_kernel<<<NBLK, 256, 65536>>>(Whh, traj_len, out);

    (void)in_sizes; (void)n_in; (void)out_size;
}

// round 11
// speedup vs baseline: 1.9352x; 1.3060x over previous
#include <cuda_runtime.h>
#include <cstdint>
#include <cstddef>

#define TT 512
#define NBATCH 256
#define EE 256
#define HH 256
#define GG 1024
#define NBLK 128
#define GSIZE 8          // CTAs per row-group (bj = 0..7)
#define NGROUPS 16       // row groups (bn = 0..15)

typedef unsigned long long ull;
union F2U { ull u; float2 f; };

// ---- packed f32x2 helpers (Blackwell FFMA2 — PTX-only, ptxas never fuses) ----
__device__ __forceinline__ ull bcast2(float x) {
    ull r; asm("mov.b64 %0, {%1, %1};" : "=l"(r) : "f"(x)); return r;
}
__device__ __forceinline__ ull pack2(float lo, float hi) {
    ull r; asm("mov.b64 %0, {%1, %2};" : "=l"(r) : "f"(lo), "f"(hi)); return r;
}
__device__ __forceinline__ void ffma2(ull& d, ull a, ull b) {
    asm("fma.rn.f32x2 %0, %1, %2, %0;" : "+l"(d) : "l"(a), "l"(b));
}

// ---------------- device scratch (no allocations allowed) ----------------
__device__ __align__(16) float g_xg[(size_t)TT * NBATCH * GG];   // xg[t][n][g]
__device__ __align__(16) float g_hbuf[2][NBATCH * HH];           // double-buffered h
__device__ __align__(128) unsigned int g_gbar[NGROUPS * 32];     // per-group tickets, 128B apart

// ---------------- phase 1: xg = x @ Wih^T + b_ih + b_hh  (+ fused state reset) ----------------
// 128x128 block tile, BK=16, 256 threads, FFMA2 accumulation (4 row-pairs x 8 cols),
// double-buffered smem. Blocks (gt==0, mt<=64) also reset h0/barriers for graph replay.
__global__ void __launch_bounds__(256, 2) xg_gemm_kernel(
    const float* __restrict__ attn,   // (N, T, E)
    const float* __restrict__ Wih,    // (4H, E)
    const float* __restrict__ bih,
    const float* __restrict__ bhh) {
    __shared__ float As[2][16][132];   // [buf][k][m]
    __shared__ float Bs[2][16][132];   // [buf][k][g]

    const int gt = blockIdx.x;                 // 0..7
    const int mt = blockIdx.y;                 // 0..1023
    const int t  = mt >> 1;
    const int n0 = (mt & 1) << 7;
    const int g0 = gt << 7;
    const int tid = threadIdx.x;
    const int tx = tid & 15;
    const int tyy = tid >> 4;                  // 0..15

    // fused graph-replay-safe reset (runs before lstm_rec in stream order)
    if (gt == 0) {
        if (mt < 64) {
            int i = (mt << 8) + tid;           // 0..16383 float4 slots
            *(float4*)&g_hbuf[0][i << 2] = make_float4(0.f, 0.f, 0.f, 0.f);
        } else if (mt == 64) {
            // NGROUPS*32 = 512 entries, blockDim = 256 -> two per thread
            g_gbar[tid] = 0u;
            g_gbar[tid + 256] = 0u;
        }
    }

    const int lr = tid >> 1;                   // loader row 0..127
    const int lk = (tid & 1) << 3;             // k offset 0 or 8

    const float* Arow = &attn[((size_t)(n0 + lr) * TT + t) * EE];
    const float* Brow = &Wih[(size_t)(g0 + lr) * EE];

    ull acc2[4][8];
#pragma unroll
    for (int i = 0; i < 4; i++)
#pragma unroll
        for (int j = 0; j < 8; j++) acc2[i][j] = 0ull;

    float4 a0, a1, b0, b1;

    a0 = *(const float4*)&Arow[lk];
    a1 = *(const float4*)&Arow[lk + 4];
    b0 = *(const float4*)&Brow[lk];
    b1 = *(const float4*)&Brow[lk + 4];
    {
        float av[8] = {a0.x, a0.y, a0.z, a0.w, a1.x, a1.y, a1.z, a1.w};
        float bv[8] = {b0.x, b0.y, b0.z, b0.w, b1.x, b1.y, b1.z, b1.w};
#pragma unroll
        for (int q = 0; q < 8; q++) { As[0][lk + q][lr] = av[q]; Bs[0][lk + q][lr] = bv[q]; }
    }
    __syncthreads();

    const int NKT = EE / 16;
#pragma unroll 1
    for (int kt = 0; kt < NKT; kt++) {
        const int cur = kt & 1, nxt = cur ^ 1;
        if (kt + 1 < NKT) {
            const int k0 = (kt + 1) << 4;
            a0 = *(const float4*)&Arow[k0 + lk];
            a1 = *(const float4*)&Arow[k0 + lk + 4];
            b0 = *(const float4*)&Brow[k0 + lk];
            b1 = *(const float4*)&Brow[k0 + lk + 4];
        }
#pragma unroll
        for (int k = 0; k < 16; k++) {
            ulonglong2 aP0 = *(const ulonglong2*)&As[cur][k][tyy << 2];
            ulonglong2 aP1 = *(const ulonglong2*)&As[cur][k][64 + (tyy << 2)];
            ull ap[4] = {aP0.x, aP0.y, aP1.x, aP1.y};
            float4 bA = *(const float4*)&Bs[cur][k][tx << 2];
            float4 bB = *(const float4*)&Bs[cur][k][64 + (tx << 2)];
            ull bb[8] = {bcast2(bA.x), bcast2(bA.y), bcast2(bA.z), bcast2(bA.w),
                         bcast2(bB.x), bcast2(bB.y), bcast2(bB.z), bcast2(bB.w)};
#pragma unroll
            for (int ip = 0; ip < 4; ip++)
#pragma unroll
                for (int j = 0; j < 8; j++) ffma2(acc2[ip][j], ap[ip], bb[j]);
        }
        if (kt + 1 < NKT) {
            float av[8] = {a0.x, a0.y, a0.z, a0.w, a1.x, a1.y, a1.z, a1.w};
            float bv[8] = {b0.x, b0.y, b0.z, b0.w, b1.x, b1.y, b1.z, b1.w};
#pragma unroll
            for (int q = 0; q < 8; q++) { As[nxt][lk + q][lr] = av[q]; Bs[nxt][lk + q][lr] = bv[q]; }
        }
        __syncthreads();
    }

    float bias[2][4];
#pragma unroll
    for (int jh = 0; jh < 2; jh++)
#pragma unroll
        for (int j = 0; j < 4; j++) {
            int g = g0 + (jh << 6) + (tx << 2) + j;
            bias[jh][j] = bih[g] + bhh[g];
        }
#pragma unroll
    for (int rr = 0; rr < 8; rr++) {
        const int ih = rr >> 2, i = rr & 3;
        const int ip = (ih << 1) | (i >> 1);
        const int hi = i & 1;
        int n = n0 + (ih << 6) + (tyy << 2) + i;
        size_t base = ((size_t)t * NBATCH + n) * GG + g0;
        float c[8];
#pragma unroll
        for (int j = 0; j < 8; j++) {
            F2U u; u.u = acc2[ip][j];
            c[j] = hi ? u.f.y : u.f.x;
        }
        float4 v0 = make_float4(c[0] + bias[0][0], c[1] + bias[0][1],
                                c[2] + bias[0][2], c[3] + bias[0][3]);
        float4 v1 = make_float4(c[4] + bias[1][0], c[5] + bias[1][1],
                                c[6] + bias[1][2], c[7] + bias[1][3]);
        *(float4*)&g_xg[base + (tx << 2)]      = v0;
        *(float4*)&g_xg[base + 64 + (tx << 2)] = v1;
    }
}

// ---------------- phase 2: persistent recurrent kernel ----------------
__device__ __forceinline__ float sigf(float x) { return 1.0f / (1.0f + __expf(-x)); }
__device__ __forceinline__ float tanh_fast(float x) { return 1.0f - 2.0f / (__expf(2.0f * x) + 1.0f); }

// 128 CTAs in 16 independent groups of 8 (group = same 16 batch rows).
// Each step: group-local 8-CTA ticket barrier -> stage 16KB h tile to smem ->
// FFMA2 partials from registers-resident packed Whh -> smem reduce -> gates.
__global__ void __launch_bounds__(256, 1) lstm_rec_kernel(
    const float* __restrict__ Whh,       // (4H, H)
    const int*   __restrict__ traj_len,  // (N,)
    float*       __restrict__ out) {     // (N, 1, H)
    extern __shared__ float red[];       // [8][16][128] = 64 KB dynamic
    __shared__ float hs[16 * 256];       // staged h tile (16 KB)
    __shared__ int slen[16];

    const int tid = threadIdx.x;
    const int bid = blockIdx.x;
    const int bn = bid & 15, bj = bid >> 4;
    const int r0 = bn << 4;
    const int c0 = bj << 5;
    const int ks = tid >> 5, gcg = tid & 31;

    // pack W_hh slice into f32x2 gate-pair registers
    ull pwA[32], pwB[32];
    {
        const float* wr[4];
#pragma unroll
        for (int q = 0; q < 4; q++) {
            int l = (gcg << 2) + q;
            int gr = ((l >> 5) << 8) + c0 + (l & 31);
            wr[q] = &Whh[(size_t)gr * HH + (ks << 5)];
        }
#pragma unroll
        for (int kc = 0; kc < 8; kc++) {
            float4 w0 = *(const float4*)(wr[0] + (kc << 2));
            float4 w1 = *(const float4*)(wr[1] + (kc << 2));
            float4 w2 = *(const float4*)(wr[2] + (kc << 2));
            float4 w3 = *(const float4*)(wr[3] + (kc << 2));
            pwA[(kc << 2) + 0] = pack2(w0.x, w1.x);
            pwA[(kc << 2) + 1] = pack2(w0.y, w1.y);
            pwA[(kc << 2) + 2] = pack2(w0.z, w1.z);
            pwA[(kc << 2) + 3] = pack2(w0.w, w1.w);
            pwB[(kc << 2) + 0] = pack2(w2.x, w3.x);
            pwB[(kc << 2) + 1] = pack2(w2.y, w3.y);
            pwB[(kc << 2) + 2] = pack2(w2.z, w3.z);
            pwB[(kc << 2) + 3] = pack2(w2.w, w3.w);
        }
    }

    if (tid < 16) slen[tid] = traj_len[r0 + tid];

    const int er = tid >> 4, ep = tid & 15;
    const int n_e = r0 + er;
    const int len_e = traj_len[n_e];
    const int col_e = c0 + (ep << 1);
    float cc0 = 0.f, cc1 = 0.f, hk0 = 0.f, hk1 = 0.f;

    unsigned int* barp = &g_gbar[bn << 5];
    __syncthreads();

    int gmax = 0;
#pragma unroll
    for (int r = 0; r < 16; r++) gmax = max(gmax, slen[r]);

    for (int t = 0; t < gmax; t++) {
        const bool valid = (t < len_e);

        // prefetch xg(t) before the spin (recurrence-independent)
        float2 xi, xf, xg2, xo;
        if (valid) {
            const float* xgp = &g_xg[((size_t)t * NBATCH + n_e) * GG + col_e];
            xi  = __ldcs((const float2*)&xgp[0]);
            xf  = __ldcs((const float2*)&xgp[256]);
            xg2 = __ldcs((const float2*)&xgp[512]);
            xo  = __ldcs((const float2*)&xgp[768]);
        }

        if (t > 0) {
            if (tid == 0) {
                const unsigned target = (unsigned)t * GSIZE;
                unsigned v;
                do {
                    asm volatile("ld.acquire.gpu.global.u32 %0, [%1];"
                                 : "=r"(v) : "l"(barp) : "memory");
                } while (v < target);
            }
            __syncthreads();
        }

        // stage this group's 16x256 h tile into smem (one coalesced 16KB load)
        {
            const float4* src = (const float4*)&g_hbuf[t & 1][r0 << 8];
#pragma unroll
            for (int q = 0; q < 4; q++) {
                int i = (q << 8) + tid;
                float4 v = __ldcg(src + i);
                *(float4*)&hs[i << 2] = v;
            }
        }
        __syncthreads();

        // GEMM partials over this warp's K-slice — skip frozen rows (uniform branch)
#pragma unroll 2
        for (int r = 0; r < 16; r++) {
            if (t < slen[r]) {
                const float4* hp = (const float4*)&hs[(r << 8) + (ks << 5)];
                ull accA = 0ull, accB = 0ull;
#pragma unroll
                for (int kc = 0; kc < 8; kc++) {
                    float4 hv = hp[kc];
                    ull h0 = bcast2(hv.x), h1 = bcast2(hv.y), h2 = bcast2(hv.z), h3 = bcast2(hv.w);
                    ffma2(accA, h0, pwA[(kc << 2) + 0]); ffma2(accB, h0, pwB[(kc << 2) + 0]);
                    ffma2(accA, h1, pwA[(kc << 2) + 1]); ffma2(accB, h1, pwB[(kc << 2) + 1]);
                    ffma2(accA, h2, pwA[(kc << 2) + 2]); ffma2(accB, h2, pwB[(kc << 2) + 2]);
                    ffma2(accA, h3, pwA[(kc << 2) + 3]); ffma2(accB, h3, pwB[(kc << 2) + 3]);
                }
                ulonglong2 st; st.x = accA; st.y = accB;
                *(ulonglong2*)&red[(((ks << 4) + r) << 7) + (gcg << 2)] = st;
            }
        }
        __syncthreads();

        if (valid) {
            float2 s[4];
#pragma unroll
            for (int typ = 0; typ < 4; typ++) {
                float sx = 0.f, sy = 0.f;
#pragma unroll
                for (int k2 = 0; k2 < 8; k2++) {
                    float2 v = *(const float2*)&red[(k2 << 11) + (er << 7) + (typ << 5) + (ep << 1)];
                    sx += v.x; sy += v.y;
                }
                s[typ] = make_float2(sx, sy);
            }
            {
                float gi = s[0].x + xi.x, gf = s[1].x + xf.x, gg = s[2].x + xg2.x, go = s[3].x + xo.x;
                float cn = sigf(gf) * cc0 + sigf(gi) * tanh_fast(gg);
                cc0 = cn; hk0 = sigf(go) * tanh_fast(cn);
            }
            {
                float gi = s[0].y + xi.y, gf = s[1].y + xf.y, gg = s[2].y + xg2.y, go = s[3].y + xo.y;
                float cn = sigf(gf) * cc1 + sigf(gi) * tanh_fast(gg);
                cc1 = cn; hk1 = sigf(go) * tanh_fast(cn);
            }
        }

        // publish h for next step (frozen rows republish last value)
        *(float2*)&g_hbuf[(t + 1) & 1][(n_e << 8) + col_e] = make_float2(hk0, hk1);

        __syncthreads();
        if (tid == 0 && t + 1 < gmax) {
            asm volatile("red.release.gpu.global.add.u32 [%0], %1;"
                         :: "l"(barp), "r"(1u) : "memory");
        }
    }

    *(float2*)&out[(n_e << 8) + col_e] = make_float2(hk0, hk1);
}

// ---------------- launch ----------------
extern "C" void kernel_launch(void* const* d_in, const int* in_sizes, int n_in,
                              void* d_out, int out_size) {
    const float* attn     = (const float*)d_in[0];   // (N, T, E)
    const int*   traj_len = (const int*)d_in[1];     // (N,)
    const float* Wih      = (const float*)d_in[2];   // (4H, E)
    const float* Whh      = (const float*)d_in[3];   // (4H, H)
    const float* bih      = (const float*)d_in[4];   // (4H,)
    const float* bhh      = (const float*)d_in[5];   // (4H,)
    float* out = (float*)d_out;

    cudaFuncSetAttribute(lstm_rec_kernel, cudaFuncAttributeMaxDynamicSharedMemorySize, 65536);

    dim3 g1(8, 1024);
    xg_gemm_kernel<<<g1, 256>>>(attn, Wih, bih, bhh);

    lstm_rec_kernel<<<NBLK, 256, 65536>>>(Whh, traj_len, out);

    (void)in_sizes; (void)n_in; (void)out_size;
}